// round 1
// baseline (speedup 1.0000x reference)
#include <cuda_runtime.h>

// Problem constants (fixed by the dataset)
#define BB 16
#define TT 128
#define UU 64
#define VV 1024
#define CELLS (BB * TT * UU)      // 131072

// Scratch (allocation-free rule: __device__ globals)
__device__ float g_lpb[CELLS];    // lp_blank[b][t][u]
__device__ float g_lpl[CELLS];    // lp_label[b][t][u] (u < UU-1 valid)
__device__ float g_cost[BB];

// ---------------------------------------------------------------------------
// FFMA-only expf: avoids MUFU (which would be the chip bottleneck at 134M ops).
// exp(x) = 2^(x*log2e). k = round(y) via magic-number add; f = y-k in [-.5,.5];
// 2^f by degree-4 poly; 2^k spliced into exponent via integer add (the magic
// constant 12582912.0f = 0x4B400000 has 9 low bits zero, so z_bits<<23 == k<<23).
// Max rel err ~5e-5. Valid for x in ~[-120, 120]; inputs are N(0,1).
// ---------------------------------------------------------------------------
__device__ __forceinline__ float fexp(float x) {
    const float C1    = 1.4426950408889634f;   // log2(e)
    const float MAGIC = 12582912.0f;           // 1.5 * 2^23
    float z = fmaf(x, C1, MAGIC);
    float d = MAGIC - z;
    float f = fmaf(x, C1, d);                  // f = x*log2e - round(x*log2e)
    float p = fmaf(f, 0.0096181291076285f, 0.0555041086648216f);
    p = fmaf(f, p, 0.2402265069591007f);
    p = fmaf(f, p, 0.6931471805599453f);
    p = fmaf(f, p, 1.0f);
    return __int_as_float(__float_as_int(p) + (__float_as_int(z) << 23));
}

// ---------------------------------------------------------------------------
// Phase 1: one warp per (b,t,u) cell. 8x float4 coalesced loads per lane,
// streaming sum of fexp into 4 independent accumulators (breaks FFMA chains),
// warp shfl reduce, lse = __logf(s) (one MUFU per cell — negligible).
// Lane 0 writes lp_blank and lp_label.
// ---------------------------------------------------------------------------
__global__ void __launch_bounds__(256) lse_kernel(const float* __restrict__ acts,
                                                  const int*   __restrict__ labels) {
    int warp = blockIdx.x * 8 + (threadIdx.x >> 5);
    int lane = threadIdx.x & 31;
    const float*  base = acts + (size_t)warp * VV;
    const float4* p4   = (const float4*)base;

    float s0 = 0.f, s1 = 0.f, s2 = 0.f, s3 = 0.f;
    float blank = 0.f;
#pragma unroll
    for (int i = 0; i < 8; i++) {
        float4 v = p4[i * 32 + lane];
        if (i == 0 && lane == 0) blank = v.x;   // acts[..., 0]
        s0 += fexp(v.x);
        s1 += fexp(v.y);
        s2 += fexp(v.z);
        s3 += fexp(v.w);
    }
    float s = (s0 + s1) + (s2 + s3);
#pragma unroll
    for (int o = 16; o; o >>= 1)
        s += __shfl_xor_sync(0xffffffffu, s, o);

    float lse = __logf(s);   // per-cell, MUFU LG2: 131072 total, trivial

    if (lane == 0) {
        g_lpb[warp] = blank - lse;
        int u = warp & (UU - 1);
        if (u < UU - 1) {
            int b   = warp >> 13;                 // warp / (TT*UU), TT*UU = 8192
            int lab = labels[b * (UU - 1) + u];
            g_lpl[warp] = base[lab] - lse;
        }
    }
}

// ---------------------------------------------------------------------------
// Phase 2: per-batch forward DP on the [T,U] lattice.
//   alpha[0,0]=0
//   alpha[t,0]=alpha[t-1,0]+lpb[t-1,0]
//   alpha[0,u]=alpha[0,u-1]+lpl[0,u-1]
//   alpha[t,u]=logaddexp(alpha[t-1,u]+lpb[t-1,u], alpha[t,u-1]+lpl[t,u-1])
// Anti-diagonal wavefront: thread u computes alpha[k-u, u] at step k.
// Left-neighbor value passed through a double-buffered shared row (one
// __syncthreads per step). lp tables staged in smem (66 KB, conflict-free:
// word index (t*64+u) mod 32 == u mod 32).
// ---------------------------------------------------------------------------
__global__ void __launch_bounds__(64) dp_kernel() {
    int b = blockIdx.x;
    int u = threadIdx.x;
    extern __shared__ float sm[];
    float* s_lpb = sm;                  // TT*UU
    float* s_lpl = sm + TT * UU;        // TT*UU
    float* s_al  = sm + 2 * TT * UU;    // 2*UU (double buffer)

    const float* gb = g_lpb + b * TT * UU;
    const float* gl = g_lpl + b * TT * UU;
    for (int i = u; i < TT * UU; i += 64) {
        s_lpb[i] = gb[i];
        s_lpl[i] = gl[i];
    }
    __syncthreads();

    float a = 0.f;
    for (int k = 0; k < TT + UU - 1; k++) {
        int t = k - u;
        if (t >= 0 && t < TT) {
            float left = (u > 0) ? s_al[((k + 1) & 1) * UU + (u - 1)] : 0.f;
            if (t == 0) {
                a = (u == 0) ? 0.f : left + s_lpl[u - 1];
            } else if (u == 0) {
                a = a + s_lpb[(t - 1) * UU];
            } else {
                float x = a    + s_lpb[(t - 1) * UU + u];
                float y = left + s_lpl[t * UU + (u - 1)];
                float M = fmaxf(x, y);
                float m = fminf(x, y);
                a = M + log1pf(__expf(m - M));
            }
        }
        s_al[(k & 1) * UU + u] = a;
        __syncthreads();
    }
    // Thread UU-1 finishes alpha[T-1,U-1] at the final step.
    if (u == UU - 1)
        g_cost[b] = -(a + s_lpb[(TT - 1) * UU + (UU - 1)]);
}

// ---------------------------------------------------------------------------
// Phase 3: deterministic mean of the 16 per-batch costs.
// ---------------------------------------------------------------------------
__global__ void reduce_kernel(float* __restrict__ out) {
    float v = (threadIdx.x < BB) ? g_cost[threadIdx.x] : 0.f;
#pragma unroll
    for (int o = 16; o; o >>= 1)
        v += __shfl_xor_sync(0xffffffffu, v, o);
    if (threadIdx.x == 0) out[0] = v * (1.0f / BB);
}

extern "C" void kernel_launch(void* const* d_in, const int* in_sizes, int n_in,
                              void* d_out, int out_size) {
    const float* acts   = (const float*)d_in[0];
    const int*   labels = (const int*)d_in[1];
    // d_in[2] = act_lens, d_in[3] = label_lens: full-length by construction, unused.

    const int smem_bytes = (2 * TT * UU + 2 * UU) * (int)sizeof(float);  // 66048
    cudaFuncSetAttribute(dp_kernel, cudaFuncAttributeMaxDynamicSharedMemorySize,
                         smem_bytes);

    lse_kernel<<<CELLS / 8, 256>>>(acts, labels);
    dp_kernel<<<BB, UU, smem_bytes>>>();
    reduce_kernel<<<1, 32>>>((float*)d_out);
}

// round 3
// speedup vs baseline: 1.4175x; 1.4175x over previous
#include <cuda_runtime.h>

// Problem constants (fixed by the dataset)
#define BB 16
#define TT 128
#define UU 64
#define VV 1024
#define CELLS (BB * TT * UU)      // 131072
#define NEGF (-1e30f)

// Scratch (allocation-free rule: __device__ globals)
__device__ float g_lpb[CELLS];    // lp_blank[b][t][u]
__device__ float g_lpl[CELLS];    // lp_label[b][t][u] (u < UU-1 valid)
__device__ float g_cost[BB];

// ---------------------------------------------------------------------------
// FFMA-only expf: avoids MUFU throughput wall at 134M ops.
// Max rel err ~5e-5 over the N(0,1) input range.
// ---------------------------------------------------------------------------
__device__ __forceinline__ float fexp(float x) {
    const float C1    = 1.4426950408889634f;   // log2(e)
    const float MAGIC = 12582912.0f;           // 1.5 * 2^23
    float z = fmaf(x, C1, MAGIC);
    float d = MAGIC - z;
    float f = fmaf(x, C1, d);                  // f = x*log2e - round(x*log2e)
    float p = fmaf(f, 0.0096181291076285f, 0.0555041086648216f);
    p = fmaf(f, p, 0.2402265069591007f);
    p = fmaf(f, p, 0.6931471805599453f);
    p = fmaf(f, p, 1.0f);
    return __int_as_float(__float_as_int(p) + (__float_as_int(z) << 23));
}

// ---------------------------------------------------------------------------
// Phase 1: one warp per (b,t,u) cell; 8x float4 streaming loads per lane.
// DRAM-bound at ~85% of peak — do not disturb.
// ---------------------------------------------------------------------------
__global__ void __launch_bounds__(256) lse_kernel(const float* __restrict__ acts,
                                                  const int*   __restrict__ labels) {
    int warp = blockIdx.x * 8 + (threadIdx.x >> 5);
    int lane = threadIdx.x & 31;
    const float*  base = acts + (size_t)warp * VV;
    const float4* p4   = (const float4*)base;

    float s0 = 0.f, s1 = 0.f, s2 = 0.f, s3 = 0.f;
    float blank = 0.f;
#pragma unroll
    for (int i = 0; i < 8; i++) {
        float4 v = __ldcs(&p4[i * 32 + lane]);
        if (i == 0 && lane == 0) blank = v.x;   // acts[..., 0]
        s0 += fexp(v.x);
        s1 += fexp(v.y);
        s2 += fexp(v.z);
        s3 += fexp(v.w);
    }
    float s = (s0 + s1) + (s2 + s3);
#pragma unroll
    for (int o = 16; o; o >>= 1)
        s += __shfl_xor_sync(0xffffffffu, s, o);

    float lse = __logf(s);

    if (lane == 0) {
        g_lpb[warp] = blank - lse;
        int u = warp & (UU - 1);
        if (u < UU - 1) {
            int b   = warp >> 13;                 // warp / (TT*UU)
            int lab = labels[b * (UU - 1) + u];
            g_lpl[warp] = base[lab] - lse;
        }
    }
}

// ---------------------------------------------------------------------------
// Phase 2: per-batch forward DP, ONE WARP per batch, 2 u-cells per lane.
// Anti-diagonal wavefront, left-neighbor via shfl_up (no __syncthreads in
// the 191-step loop). NEG sentinels keep the update branch-free. Frozen
// cells (t outside [0,TT)) keep their last value, which is exactly the
// previous-diagonal value the right neighbor needs.
// Operand indices are clamped to [0, TT-1] — loads for frozen cells are
// dead values but must stay in-bounds (R2 bug: upper clamp was missing).
// ---------------------------------------------------------------------------
__global__ void __launch_bounds__(256) dp_kernel() {
    int b = blockIdx.x;
    extern __shared__ float sm[];
    float* s_lpb = sm;                  // TT*UU
    float* s_lpl = sm + TT * UU;        // TT*UU

    // Stage both lp tables with all 256 threads (float4).
    {
        const float4* gb = (const float4*)(g_lpb + b * TT * UU);
        const float4* gl = (const float4*)(g_lpl + b * TT * UU);
        float4* sb = (float4*)s_lpb;
        float4* sl = (float4*)s_lpl;
        int tid = threadIdx.x;
#pragma unroll
        for (int i = 0; i < (TT * UU / 4) / 256; i++) {   // 8 iters
            sb[i * 256 + tid] = gb[i * 256 + tid];
            sl[i * 256 + tid] = gl[i * 256 + tid];
        }
    }
    __syncthreads();
    if (threadIdx.x >= 32) return;      // warp 0 runs the DP alone

    int lane = threadIdx.x;
    int u_lo = lane * 2;
    int u_hi = u_lo + 1;
    float a_lo = NEGF, a_hi = NEGF;

    for (int k = 0; k < TT + UU - 1; k++) {
        // previous-diagonal left neighbors
        float left_lo = __shfl_up_sync(0xffffffffu, a_hi, 1);
        if (lane == 0) left_lo = NEGF;
        float left_hi = a_lo;

        int t_lo = k - u_lo;
        int t_hi = k - u_hi;

        // clamped operand indices (both sides!)
        int tb_lo = min(max(t_lo - 1, 0), TT - 1);
        int tl_lo = min(max(t_lo, 0), TT - 1);
        int tb_hi = min(max(t_hi - 1, 0), TT - 1);
        int tl_hi = min(max(t_hi, 0), TT - 1);

        float lpb_lo = s_lpb[tb_lo * UU + u_lo];
        float lpl_lo = s_lpl[tl_lo * UU + max(u_lo - 1, 0)];
        float lpb_hi = s_lpb[tb_hi * UU + u_hi];
        float lpl_hi = s_lpl[tl_hi * UU + u_lo];

        // lo cell
        {
            float x = a_lo + lpb_lo;
            float y = left_lo + lpl_lo;
            float M = fmaxf(x, y), m = fminf(x, y);
            float n = M + __logf(1.0f + __expf(m - M));
            if (k == 0 && lane == 0) n = 0.0f;          // seed alpha[0,0]
            if (t_lo >= 0 && t_lo < TT) a_lo = n;       // freeze outside lattice
        }
        // hi cell (independent of lo's update this step)
        {
            float x = a_hi + lpb_hi;
            float y = left_hi + lpl_hi;
            float M = fmaxf(x, y), m = fminf(x, y);
            float n = M + __logf(1.0f + __expf(m - M));
            if (t_hi >= 0 && t_hi < TT) a_hi = n;
        }
    }

    if (lane == 31)
        g_cost[b] = -(a_hi + s_lpb[(TT - 1) * UU + (UU - 1)]);
}

// ---------------------------------------------------------------------------
// Phase 3: deterministic mean of the 16 per-batch costs.
// ---------------------------------------------------------------------------
__global__ void reduce_kernel(float* __restrict__ out) {
    float v = (threadIdx.x < BB) ? g_cost[threadIdx.x] : 0.f;
#pragma unroll
    for (int o = 16; o; o >>= 1)
        v += __shfl_xor_sync(0xffffffffu, v, o);
    if (threadIdx.x == 0) out[0] = v * (1.0f / BB);
}

extern "C" void kernel_launch(void* const* d_in, const int* in_sizes, int n_in,
                              void* d_out, int out_size) {
    const float* acts   = (const float*)d_in[0];
    const int*   labels = (const int*)d_in[1];

    const int smem_bytes = 2 * TT * UU * (int)sizeof(float);  // 65536
    cudaFuncSetAttribute(dp_kernel, cudaFuncAttributeMaxDynamicSharedMemorySize,
                         smem_bytes);

    lse_kernel<<<CELLS / 8, 256>>>(acts, labels);
    dp_kernel<<<BB, 256, smem_bytes>>>();
    reduce_kernel<<<1, 32>>>((float*)d_out);
}

// round 4
// speedup vs baseline: 1.4425x; 1.0176x over previous
#include <cuda_runtime.h>

// Problem constants (fixed by the dataset)
#define BB 16
#define TT 128
#define UU 64
#define VV 1024
#define CELLS (BB * TT * UU)      // 131072
#define NEGF   (-1e30f)
#define LOG2EF 1.4426950408889634f
#define LN2F   0.6931471805599453f

// Scratch (allocation-free rule: __device__ globals)
// NOTE: lp tables are stored PRE-SCALED by log2(e) (log2-domain DP).
__device__ float g_lpb[CELLS];    // lp_blank[b][t][u] * log2e
__device__ float g_lpl[CELLS];    // lp_label[b][t][u] * log2e (u < UU-1 valid)
__device__ float g_cost[BB];      // nat-domain per-batch cost
__device__ int   g_ticket;        // last-block-done counter (zero-init; reset by winner)

// ---------------------------------------------------------------------------
// FFMA-only expf: avoids the MUFU throughput wall at 134M ops.
// ---------------------------------------------------------------------------
__device__ __forceinline__ float fexp(float x) {
    const float C1    = 1.4426950408889634f;   // log2(e)
    const float MAGIC = 12582912.0f;           // 1.5 * 2^23
    float z = fmaf(x, C1, MAGIC);
    float d = MAGIC - z;
    float f = fmaf(x, C1, d);                  // f = x*log2e - round(x*log2e)
    float p = fmaf(f, 0.0096181291076285f, 0.0555041086648216f);
    p = fmaf(f, p, 0.2402265069591007f);
    p = fmaf(f, p, 0.6931471805599453f);
    p = fmaf(f, p, 1.0f);
    return __int_as_float(__float_as_int(p) + (__float_as_int(z) << 23));
}

__device__ __forceinline__ float fast_ex2(float x) {
    float r; asm("ex2.approx.ftz.f32 %0, %1;" : "=f"(r) : "f"(x)); return r;
}
__device__ __forceinline__ float fast_lg2(float x) {
    float r; asm("lg2.approx.ftz.f32 %0, %1;" : "=f"(r) : "f"(x)); return r;
}

// ---------------------------------------------------------------------------
// Phase 1: one warp per (b,t,u) cell. All 8 float4 loads issued up-front
// (MLP=8/lane) before any math; streaming (__ldcs) since data is read once.
// Writes log2-scaled lp values.
// ---------------------------------------------------------------------------
__global__ void __launch_bounds__(256) lse_kernel(const float* __restrict__ acts,
                                                  const int*   __restrict__ labels) {
    int warp = blockIdx.x * 8 + (threadIdx.x >> 5);
    int lane = threadIdx.x & 31;
    const float*  base = acts + (size_t)warp * VV;
    const float4* p4   = (const float4*)base;

    float4 v[8];
#pragma unroll
    for (int i = 0; i < 8; i++)
        v[i] = __ldcs(&p4[i * 32 + lane]);

    float blank = v[0].x;                      // valid on lane 0 only
    float s0 = 0.f, s1 = 0.f, s2 = 0.f, s3 = 0.f;
#pragma unroll
    for (int i = 0; i < 8; i++) {
        s0 += fexp(v[i].x);
        s1 += fexp(v[i].y);
        s2 += fexp(v[i].z);
        s3 += fexp(v[i].w);
    }
    float s = (s0 + s1) + (s2 + s3);
#pragma unroll
    for (int o = 16; o; o >>= 1)
        s += __shfl_xor_sync(0xffffffffu, s, o);

    float lse2 = fast_lg2(s);                  // log2-domain lse

    if (lane == 0) {
        g_lpb[warp] = fmaf(blank, LOG2EF, -lse2);
        int u = warp & (UU - 1);
        if (u < UU - 1) {
            int b   = warp >> 13;              // warp / (TT*UU)
            int lab = labels[b * (UU - 1) + u];
            g_lpl[warp] = fmaf(base[lab], LOG2EF, -lse2);
        }
    }
}

// ---------------------------------------------------------------------------
// Phase 2+3: per-batch forward DP, ONE WARP per batch, 2 u-cells per lane,
// log2-domain: logaddexp2(x,y) = M + lg2(1 + ex2(min-M)) — bare MUFUs, no
// scale multiplies on the 191-step critical chain. Left neighbor via shfl.
// Final mean folded in via last-block-done ticket (fixed summation order ->
// bit-deterministic; winner resets the ticket for graph replays).
// ---------------------------------------------------------------------------
__global__ void __launch_bounds__(256) dp_kernel(float* __restrict__ out) {
    int b = blockIdx.x;
    extern __shared__ float sm[];
    float* s_lpb = sm;                  // TT*UU
    float* s_lpl = sm + TT * UU;        // TT*UU

    // Stage both (pre-scaled) lp tables with all 256 threads (float4).
    {
        const float4* gb = (const float4*)(g_lpb + b * TT * UU);
        const float4* gl = (const float4*)(g_lpl + b * TT * UU);
        float4* sb = (float4*)s_lpb;
        float4* sl = (float4*)s_lpl;
        int tid = threadIdx.x;
#pragma unroll
        for (int i = 0; i < (TT * UU / 4) / 256; i++) {   // 8 iters
            sb[i * 256 + tid] = gb[i * 256 + tid];
            sl[i * 256 + tid] = gl[i * 256 + tid];
        }
    }
    __syncthreads();
    if (threadIdx.x >= 32) return;      // warp 0 runs the DP alone

    int lane = threadIdx.x;
    int u_lo = lane * 2;
    int u_hi = u_lo + 1;
    float a_lo = NEGF, a_hi = NEGF;

    for (int k = 0; k < TT + UU - 1; k++) {
        // previous-diagonal left neighbors
        float left_lo = __shfl_up_sync(0xffffffffu, a_hi, 1);
        if (lane == 0) left_lo = NEGF;
        float left_hi = a_lo;

        int t_lo = k - u_lo;
        int t_hi = k - u_hi;

        // clamped operand indices (both sides — frozen cells load dead but
        // in-bounds values)
        int tb_lo = min(max(t_lo - 1, 0), TT - 1);
        int tl_lo = min(max(t_lo, 0), TT - 1);
        int tb_hi = min(max(t_hi - 1, 0), TT - 1);
        int tl_hi = min(max(t_hi, 0), TT - 1);

        float lpb_lo = s_lpb[tb_lo * UU + u_lo];
        float lpl_lo = s_lpl[tl_lo * UU + max(u_lo - 1, 0)];
        float lpb_hi = s_lpb[tb_hi * UU + u_hi];
        float lpl_hi = s_lpl[tl_hi * UU + u_lo];

        // lo cell
        {
            float x = a_lo + lpb_lo;
            float y = left_lo + lpl_lo;
            float M = fmaxf(x, y);
            float d = fminf(x, y) - M;
            float n = M + fast_lg2(1.0f + fast_ex2(d));
            if (k == 0 && lane == 0) n = 0.0f;          // seed alpha[0,0]
            if (t_lo >= 0 && t_lo < TT) a_lo = n;       // freeze outside lattice
        }
        // hi cell (independent of lo's update this step)
        {
            float x = a_hi + lpb_hi;
            float y = left_hi + lpl_hi;
            float M = fmaxf(x, y);
            float d = fminf(x, y) - M;
            float n = M + fast_lg2(1.0f + fast_ex2(d));
            if (t_hi >= 0 && t_hi < TT) a_hi = n;
        }
    }

    // lane 31 holds alpha2[T-1, U-1]; convert back to nat domain.
    int is_last = 0;
    if (lane == 31) {
        g_cost[b] = -(a_hi + s_lpb[(TT - 1) * UU + (UU - 1)]) * LN2F;
        __threadfence();                                 // publish before ticket
        is_last = (atomicAdd(&g_ticket, 1) == BB - 1);
    }
    is_last = __shfl_sync(0xffffffffu, is_last, 31);

    if (is_last) {
        float v = (lane < BB) ? __ldcg(&g_cost[lane]) : 0.f;
#pragma unroll
        for (int o = 16; o; o >>= 1)
            v += __shfl_xor_sync(0xffffffffu, v, o);
        if (lane == 0) {
            out[0] = v * (1.0f / BB);
            g_ticket = 0;                                // reset for next replay
        }
    }
}

extern "C" void kernel_launch(void* const* d_in, const int* in_sizes, int n_in,
                              void* d_out, int out_size) {
    const float* acts   = (const float*)d_in[0];
    const int*   labels = (const int*)d_in[1];

    const int smem_bytes = 2 * TT * UU * (int)sizeof(float);  // 65536
    cudaFuncSetAttribute(dp_kernel, cudaFuncAttributeMaxDynamicSharedMemorySize,
                         smem_bytes);

    lse_kernel<<<CELLS / 8, 256>>>(acts, labels);
    dp_kernel<<<BB, 256, smem_bytes>>>((float*)d_out);
}

// round 5
// speedup vs baseline: 1.4684x; 1.0179x over previous
#include <cuda_runtime.h>

// Problem constants (fixed by the dataset)
#define BB 16
#define TT 128
#define UU 64
#define VV 1024
#define CELLS (BB * TT * UU)      // 131072
#define NEGF   (-1e30f)
#define LOG2EF 1.4426950408889634f
#define LN2F   0.6931471805599453f

// Scratch (allocation-free rule: __device__ globals)
// lp tables stored PRE-SCALED by log2(e) (log2-domain DP).
__device__ float g_lpb[CELLS];    // lp_blank * log2e
__device__ float g_lpl[CELLS];    // lp_label * log2e (u < UU-1 valid; col 63 stays 0)
__device__ float g_cost[BB];
__device__ int   g_ticket;        // last-block-done counter (zero-init; winner resets)

// ---------------------------------------------------------------------------
// FFMA-only expf (phase-1 bulk): avoids MUFU throughput wall at 134M ops.
// ---------------------------------------------------------------------------
__device__ __forceinline__ float fexp(float x) {
    const float C1    = 1.4426950408889634f;
    const float MAGIC = 12582912.0f;           // 1.5 * 2^23
    float z = fmaf(x, C1, MAGIC);
    float d = MAGIC - z;
    float f = fmaf(x, C1, d);
    float p = fmaf(f, 0.0096181291076285f, 0.0555041086648216f);
    p = fmaf(f, p, 0.2402265069591007f);
    p = fmaf(f, p, 0.6931471805599453f);
    p = fmaf(f, p, 1.0f);
    return __int_as_float(__float_as_int(p) + (__float_as_int(z) << 23));
}

__device__ __forceinline__ float fast_ex2(float x) {
    float r; asm("ex2.approx.ftz.f32 %0, %1;" : "=f"(r) : "f"(x)); return r;
}
__device__ __forceinline__ float fast_lg2(float x) {
    float r; asm("lg2.approx.ftz.f32 %0, %1;" : "=f"(r) : "f"(x)); return r;
}

// ---------------------------------------------------------------------------
// Phase 1: one warp per (b,t,u) cell; 8 front-batched float4 streaming loads.
// At 86.6% DRAM — the streaming floor; unchanged.
// ---------------------------------------------------------------------------
__global__ void __launch_bounds__(256) lse_kernel(const float* __restrict__ acts,
                                                  const int*   __restrict__ labels) {
    int warp = blockIdx.x * 8 + (threadIdx.x >> 5);
    int lane = threadIdx.x & 31;
    const float*  base = acts + (size_t)warp * VV;
    const float4* p4   = (const float4*)base;

    float4 v[8];
#pragma unroll
    for (int i = 0; i < 8; i++)
        v[i] = __ldcs(&p4[i * 32 + lane]);

    float blank = v[0].x;                      // valid on lane 0 only
    float s0 = 0.f, s1 = 0.f, s2 = 0.f, s3 = 0.f;
#pragma unroll
    for (int i = 0; i < 8; i++) {
        s0 += fexp(v[i].x);
        s1 += fexp(v[i].y);
        s2 += fexp(v[i].z);
        s3 += fexp(v[i].w);
    }
    float s = (s0 + s1) + (s2 + s3);
#pragma unroll
    for (int o = 16; o; o >>= 1)
        s += __shfl_xor_sync(0xffffffffu, s, o);

    float lse2 = fast_lg2(s);                  // log2-domain lse

    if (lane == 0) {
        g_lpb[warp] = fmaf(blank, LOG2EF, -lse2);
        int u = warp & (UU - 1);
        if (u < UU - 1) {
            int b   = warp >> 13;
            int lab = labels[b * (UU - 1) + u];
            g_lpl[warp] = fmaf(base[lab], LOG2EF, -lse2);
        }
    }
}

// ---------------------------------------------------------------------------
// Phase 2+3: per-batch DP, one warp per batch, 2 u-cells per lane.
// Log2-domain, PREDICATE-FREE inner loop:
//  * smem tables have 4096-float zero guards front+back; sentinel -1e30 is a
//    fixed point of the update (absorbing adds; ex2(-huge)=0 -> n = max
//    exactly), so out-of-range cells need no range checks.
//  * all four operand addresses are immediate offsets {0,-63,+16384,+16447}
//    off ONE running index A (A += 64 per step) — no per-step index math.
//  * shfl for step k+1 issued right after a_hi(k) — latency hidden.
// Lane 0's missing left neighbor: lpl_lo := NEG (loop-invariant predicate),
// which absorbs the bogus shfl value exactly.
// smem layout (floats): [0,4096) guard | [4096,12288) lpb | [12288,16384) guard
//                       [16384,20480) guard | [20480,28672) lpl | [28672,32768) guard
// ---------------------------------------------------------------------------
__global__ void __launch_bounds__(256) dp_kernel(float* __restrict__ out) {
    int b = blockIdx.x;
    extern __shared__ float sm[];
    float4* s4 = (float4*)sm;
    int tid = threadIdx.x;

    // zero the four guard zones (each 4096 floats = 1024 float4)
    float4 z4 = make_float4(0.f, 0.f, 0.f, 0.f);
#pragma unroll
    for (int i = 0; i < 4; i++) {
        int j = i * 256 + tid;
        s4[j]        = z4;   // lpb front
        s4[3072 + j] = z4;   // lpb back
        s4[4096 + j] = z4;   // lpl front
        s4[7168 + j] = z4;   // lpl back
    }
    // stage the two 8192-float tables into the middles
    {
        const float4* gb = (const float4*)(g_lpb + b * TT * UU);
        const float4* gl = (const float4*)(g_lpl + b * TT * UU);
#pragma unroll
        for (int i = 0; i < 8; i++) {
            int j = i * 256 + tid;
            s4[1024 + j] = gb[j];
            s4[5120 + j] = gl[j];
        }
    }
    __syncthreads();
    if (tid >= 32) return;              // warp 0 runs the DP

    int lane = tid;
    int u_lo = lane * 2;
    bool lane0 = (lane == 0);

    // k=0 peeled: only cell (0,0) is live.
    float a_lo = lane0 ? 0.f : NEGF;
    float a_hi = NEGF;

    int A = 4096 - 63 * u_lo;           // float index for k=1
    float nl = __shfl_up_sync(0xffffffffu, a_hi, 1);   // left for k=1 (NEG everywhere)

#pragma unroll 2
    for (int k = 1; k < TT + UU - 1; k++) {
        float left_lo = nl;
        float left_hi = a_lo;

        float lpb_lo = sm[A];
        float lpb_hi = sm[A - 63];
        float lpl_hi = sm[A + 16384];
        float lpl_lo = lane0 ? NEGF : sm[A + 16384 + 63];
        A += 64;

        // lo cell
        float x0 = a_lo + lpb_lo;
        float y0 = left_lo + lpl_lo;
        float M0 = fmaxf(x0, y0);
        float t0 = x0 - y0;
        float d0 = fminf(t0, -t0);              // -|x-y|
        a_lo = M0 + fast_lg2(1.0f + fast_ex2(d0));

        // hi cell (left neighbor is in-lane: old a_lo)
        float x1 = a_hi + lpb_hi;
        float y1 = left_hi + lpl_hi;
        float M1 = fmaxf(x1, y1);
        float t1 = x1 - y1;
        float d1 = fminf(t1, -t1);
        a_hi = M1 + fast_lg2(1.0f + fast_ex2(d1));

        nl = __shfl_up_sync(0xffffffffu, a_hi, 1);  // pipelined for k+1
    }

    // lane 31 holds alpha2[T-1, U-1]; add final blank, back to nat domain.
    int is_last = 0;
    if (lane == 31) {
        g_cost[b] = -(a_hi + sm[4096 + (TT - 1) * UU + (UU - 1)]) * LN2F;
        __threadfence();
        is_last = (atomicAdd(&g_ticket, 1) == BB - 1);
    }
    is_last = __shfl_sync(0xffffffffu, is_last, 31);

    if (is_last) {
        float v = (lane < BB) ? __ldcg(&g_cost[lane]) : 0.f;
#pragma unroll
        for (int o = 16; o; o >>= 1)
            v += __shfl_xor_sync(0xffffffffu, v, o);
        if (lane == 0) {
            out[0] = v * (1.0f / BB);
            g_ticket = 0;                        // reset for next graph replay
        }
    }
}

extern "C" void kernel_launch(void* const* d_in, const int* in_sizes, int n_in,
                              void* d_out, int out_size) {
    const float* acts   = (const float*)d_in[0];
    const int*   labels = (const int*)d_in[1];

    const int smem_bytes = 32768 * (int)sizeof(float);  // 131072
    cudaFuncSetAttribute(dp_kernel, cudaFuncAttributeMaxDynamicSharedMemorySize,
                         smem_bytes);

    lse_kernel<<<CELLS / 8, 256>>>(acts, labels);
    dp_kernel<<<BB, 256, smem_bytes>>>((float*)d_out);
}

// round 6
// speedup vs baseline: 1.5043x; 1.0245x over previous
#include <cuda_runtime.h>

// Problem constants (fixed by the dataset)
#define BB 16
#define TT 128
#define UU 64
#define VV 1024
#define CELLS (BB * TT * UU)      // 131072
#define NEGF   (-1e30f)
#define LOG2EF 1.4426950408889634f
#define LN2F   0.6931471805599453f

// Scratch (allocation-free rule: __device__ globals)
// lp tables stored PRE-SCALED by log2(e) (log2-domain DP).
__device__ float g_lpb[CELLS];    // lp_blank * log2e
__device__ float g_lpl[CELLS];    // lp_label * log2e (u < UU-1 valid)
__device__ float g_cost[BB];
__device__ int   g_ticket;        // last-block-done counter (zero-init; winner resets)

// ---------------------------------------------------------------------------
// FFMA-only expf (phase-1 bulk): avoids MUFU throughput wall at 134M ops.
// ---------------------------------------------------------------------------
__device__ __forceinline__ float fexp(float x) {
    const float C1    = 1.4426950408889634f;
    const float MAGIC = 12582912.0f;           // 1.5 * 2^23
    float z = fmaf(x, C1, MAGIC);
    float d = MAGIC - z;
    float f = fmaf(x, C1, d);
    float p = fmaf(f, 0.0096181291076285f, 0.0555041086648216f);
    p = fmaf(f, p, 0.2402265069591007f);
    p = fmaf(f, p, 0.6931471805599453f);
    p = fmaf(f, p, 1.0f);
    return __int_as_float(__float_as_int(p) + (__float_as_int(z) << 23));
}

__device__ __forceinline__ float fast_ex2(float x) {
    float r; asm("ex2.approx.ftz.f32 %0, %1;" : "=f"(r) : "f"(x)); return r;
}
__device__ __forceinline__ float fast_lg2(float x) {
    float r; asm("lg2.approx.ftz.f32 %0, %1;" : "=f"(r) : "f"(x)); return r;
}

// ---------------------------------------------------------------------------
// Phase 1: one warp per (b,t,u) cell; 8 front-batched float4 streaming loads.
// At 86.6% DRAM — the streaming floor; unchanged.
// ---------------------------------------------------------------------------
__global__ void __launch_bounds__(256) lse_kernel(const float* __restrict__ acts,
                                                  const int*   __restrict__ labels) {
    int warp = blockIdx.x * 8 + (threadIdx.x >> 5);
    int lane = threadIdx.x & 31;
    const float*  base = acts + (size_t)warp * VV;
    const float4* p4   = (const float4*)base;

    float4 v[8];
#pragma unroll
    for (int i = 0; i < 8; i++)
        v[i] = __ldcs(&p4[i * 32 + lane]);

    float blank = v[0].x;                      // valid on lane 0 only
    float s0 = 0.f, s1 = 0.f, s2 = 0.f, s3 = 0.f;
#pragma unroll
    for (int i = 0; i < 8; i++) {
        s0 += fexp(v[i].x);
        s1 += fexp(v[i].y);
        s2 += fexp(v[i].z);
        s3 += fexp(v[i].w);
    }
    float s = (s0 + s1) + (s2 + s3);
#pragma unroll
    for (int o = 16; o; o >>= 1)
        s += __shfl_xor_sync(0xffffffffu, s, o);

    float lse2 = fast_lg2(s);                  // log2-domain lse

    if (lane == 0) {
        g_lpb[warp] = fmaf(blank, LOG2EF, -lse2);
        int u = warp & (UU - 1);
        if (u < UU - 1) {
            int b   = warp >> 13;
            int lab = labels[b * (UU - 1) + u];
            g_lpl[warp] = fmaf(base[lab], LOG2EF, -lse2);
        }
    }
}

// ---------------------------------------------------------------------------
// Phase 2+3: 2-DIAGONAL-FUSED DP on the even sub-lattice, one warp/batch,
// 2 u-cells per lane, 95 super-steps (vs 191 plain steps).
//   alpha[t,u] = LAE3(alpha[t-2,u]+A, alpha[t-1,u-1]+B, alpha[t,u-2]+C)
// A/B/C are alpha-independent -> precomputed by ALL 256 threads into smem
// (off the serial critical path). Sentinel -1e30 absorbs every
// out-of-lattice source exactly; u<2 edges get B/C := NEG at build time, so
// the serial loop has no lane special-casing. Freeze (t > T-1) is a per-lane
// s-threshold select, off-chain.
// smem (floats): lpb[0,8192) lpl[8192,16384) wA[16384,22528)
//                wB[22528,28672) wC[28672,34816)
// ---------------------------------------------------------------------------
__global__ void __launch_bounds__(256) dp_kernel(float* __restrict__ out) {
    int b = blockIdx.x;
    extern __shared__ float sm[];
    float* s_lpb = sm;
    float* s_lpl = sm + 8192;
    float* wA    = sm + 16384;
    float* wB    = sm + 22528;
    float* wC    = sm + 28672;
    int tid = threadIdx.x;

    // Stage lp tables (float4, flat — weight build clamps indices itself).
    {
        const float4* gb = (const float4*)(g_lpb + b * TT * UU);
        const float4* gl = (const float4*)(g_lpl + b * TT * UU);
        float4* sb = (float4*)s_lpb;
        float4* sl = (float4*)s_lpl;
#pragma unroll
        for (int i = 0; i < 8; i++) {
            int j = i * 256 + tid;
            sb[j] = gb[j];
            sl[j] = gl[j];
        }
    }
    __syncthreads();

    // Build fused weights for s in [1,95], u in [0,63]: index j = s*64+u.
    for (int j = 64 + tid; j < 6144; j += 256) {
        int s = j >> 6, u = j & 63;
        int t = 2 * s - u;
        int r0 = min(max(t,     0), TT - 1);
        int r1 = min(max(t - 1, 0), TT - 1);
        int r2 = min(max(t - 2, 0), TT - 1);
        int um1 = max(u - 1, 0);
        int um2 = max(u - 2, 0);

        float b_r1u   = s_lpb[r1 * UU + u];
        float A       = s_lpb[r2 * UU + u] + b_r1u;
        float l_r0um1 = s_lpl[r0 * UU + um1];
        float B1 = s_lpl[r1 * UU + um1] + b_r1u;     // label@(t-1) then blank
        float B2 = s_lpb[r1 * UU + um1] + l_r0um1;   // blank@(t-1) then label
        float MBv = fmaxf(B1, B2);
        float B  = MBv + fast_lg2(fast_ex2(B1 - MBv) + fast_ex2(B2 - MBv));
        float C  = s_lpl[r0 * UU + um2] + l_r0um1;
        if (u == 0) B = NEGF;
        if (u < 2)  C = NEGF;
        wA[j] = A; wB[j] = B; wC[j] = C;
    }
    __syncthreads();
    if (tid >= 32) return;              // warp 0 runs the serial DP

    int lane = tid;
    int u_lo = lane * 2;

    // s=0 state: only alpha[0,0] = 0 live.
    float a_lo = (lane == 0) ? 0.f : NEGF;
    float a_hi = NEGF;
    float nl_lo = __shfl_up_sync(0xffffffffu, a_lo, 1);
    float nl_hi = __shfl_up_sync(0xffffffffu, a_hi, 1);

    int W = 64 + u_lo;                  // weight index at s=1
    int flo = 63 + lane;                // freeze thresholds: s <= flo / fhi
    int fhi = 64 + lane;

    for (int s = 1; s <= 95; s++) {
        float Alo = wA[W],     Blo = wB[W],     Clo = wC[W];
        float Ahi = wA[W + 1], Bhi = wB[W + 1], Chi = wC[W + 1];
        W += 64;

        // sources (all pre-update values)
        float x0 = a_lo  + Alo;
        float y0 = nl_hi + Blo;
        float z0 = nl_lo + Clo;
        float x1 = a_hi  + Ahi;
        float y1 = a_lo  + Bhi;
        float z1 = nl_hi + Chi;

        float M0 = fmaxf(fmaxf(x0, y0), z0);
        float e0 = fast_ex2(x0 - M0) + fast_ex2(y0 - M0) + fast_ex2(z0 - M0);
        float n0 = M0 + fast_lg2(e0);

        float M1 = fmaxf(fmaxf(x1, y1), z1);
        float e1 = fast_ex2(x1 - M1) + fast_ex2(y1 - M1) + fast_ex2(z1 - M1);
        float n1 = M1 + fast_lg2(e1);

        a_lo = (s <= flo) ? n0 : a_lo;   // freeze past t = T-1
        a_hi = (s <= fhi) ? n1 : a_hi;

        nl_lo = __shfl_up_sync(0xffffffffu, a_lo, 1);
        nl_hi = __shfl_up_sync(0xffffffffu, a_hi, 1);
    }

    // lane 31 a_hi = alpha[T-1, U-1]; add final blank, back to nat domain.
    int is_last = 0;
    if (lane == 31) {
        g_cost[b] = -(a_hi + s_lpb[(TT - 1) * UU + (UU - 1)]) * LN2F;
        __threadfence();
        is_last = (atomicAdd(&g_ticket, 1) == BB - 1);
    }
    is_last = __shfl_sync(0xffffffffu, is_last, 31);

    if (is_last) {
        float v = (lane < BB) ? __ldcg(&g_cost[lane]) : 0.f;
#pragma unroll
        for (int o = 16; o; o >>= 1)
            v += __shfl_xor_sync(0xffffffffu, v, o);
        if (lane == 0) {
            out[0] = v * (1.0f / BB);
            g_ticket = 0;                // reset for next graph replay
        }
    }
}

extern "C" void kernel_launch(void* const* d_in, const int* in_sizes, int n_in,
                              void* d_out, int out_size) {
    const float* acts   = (const float*)d_in[0];
    const int*   labels = (const int*)d_in[1];

    const int smem_bytes = 34816 * (int)sizeof(float);  // 139264
    cudaFuncSetAttribute(dp_kernel, cudaFuncAttributeMaxDynamicSharedMemorySize,
                         smem_bytes);

    lse_kernel<<<CELLS / 8, 256>>>(acts, labels);
    dp_kernel<<<BB, 256, smem_bytes>>>((float*)d_out);
}